// round 1
// baseline (speedup 1.0000x reference)
#include <cuda_runtime.h>
#include <math.h>

#define H 64
#define H3 192
#define RDIM 64
#define NMAX 50000
#define EMAX 400000

// ---- scratch (device globals; no allocation allowed) ----
__device__ float g_ref_accum[NMAX * 4];   // sum x,y,z + count
__device__ float g_ref_vec[NMAX * 3];
__device__ float g_sproj[(size_t)NMAX * H3];
__device__ float g_geom[(size_t)EMAX * 8];

// ================= kernel 1: zero output + accumulators =================
__global__ void k_zero(float* __restrict__ out, int n_out, int n_nodes) {
    int total = n_out + n_nodes * 4;
    for (int i = blockIdx.x * blockDim.x + threadIdx.x; i < total;
         i += gridDim.x * blockDim.x) {
        if (i < n_out) out[i] = 0.0f;
        else g_ref_accum[i - n_out] = 0.0f;
    }
}

// ================= kernel 2: segment-sum of edge_udiff over i =================
__global__ void k_refaccum(const float* __restrict__ ud,
                           const int* __restrict__ eidx, int E) {
    int e = blockIdx.x * blockDim.x + threadIdx.x;
    if (e >= E) return;
    int i = eidx[E + e];
    atomicAdd(&g_ref_accum[i * 4 + 0], ud[e * 3 + 0]);
    atomicAdd(&g_ref_accum[i * 4 + 1], ud[e * 3 + 1]);
    atomicAdd(&g_ref_accum[i * 4 + 2], ud[e * 3 + 2]);
    atomicAdd(&g_ref_accum[i * 4 + 3], 1.0f);
}

// ================= kernel 3: normalize ref vector per node =================
__global__ void k_refvec(int N) {
    int n = blockIdx.x * blockDim.x + threadIdx.x;
    if (n >= N) return;
    float sx = g_ref_accum[n * 4 + 0];
    float sy = g_ref_accum[n * 4 + 1];
    float sz = g_ref_accum[n * 4 + 2];
    float c  = g_ref_accum[n * 4 + 3];
    float ic = 1.0f / fmaxf(c, 1.0f);
    float rx = sx * ic, ry = sy * ic, rz = sz * ic;
    float norm = sqrtf(rx * rx + ry * ry + rz * rz + 1e-9f);
    float inm = 1.0f / norm;
    rx *= inm; ry *= inm; rz *= inm;
    if (norm < 5e-5f) { rx = 1.0f; ry = 0.0f; rz = 0.0f; }
    g_ref_vec[n * 3 + 0] = rx;
    g_ref_vec[n * 3 + 1] = ry;
    g_ref_vec[n * 3 + 2] = rz;
}

// ================= kernel 4: node scalar MLP projection =================
__global__ void __launch_bounds__(256)
k_sproj(const float* __restrict__ ns, const float* __restrict__ W1,
        const float* __restrict__ b1, const float* __restrict__ W2,
        const float* __restrict__ b2, int N) {
    __shared__ float sW1[64 * 32];
    __shared__ float sW2[32 * 192];
    __shared__ float sb1[32];
    __shared__ float sb2[192];
    int tid = threadIdx.x;
    for (int q = tid; q < 64 * 32; q += 256) sW1[q] = W1[q];
    for (int q = tid; q < 32 * 192; q += 256) sW2[q] = W2[q];
    if (tid < 32) sb1[tid] = b1[tid];
    if (tid < 192) sb2[tid] = b2[tid];
    __syncthreads();
    int lane = tid & 31, warp = tid >> 5;
    int gw = blockIdx.x * 8 + warp, nw = gridDim.x * 8;
    for (int n = gw; n < N; n += nw) {
        float a0 = ns[n * 64 + lane];
        float a1 = ns[n * 64 + 32 + lane];
        float t = sb1[lane];
#pragma unroll
        for (int r = 0; r < 64; r++) {
            float v = __shfl_sync(0xffffffffu, (r < 32) ? a0 : a1, r & 31);
            t = fmaf(v, sW1[r * 32 + lane], t);
        }
        // scaled silu
        t = t * (1.0f / (1.0f + __expf(-t))) * (1.0f / 0.6f);
        float o[6];
#pragma unroll
        for (int k = 0; k < 6; k++) o[k] = sb2[lane + 32 * k];
#pragma unroll
        for (int r = 0; r < 32; r++) {
            float v = __shfl_sync(0xffffffffu, t, r);
#pragma unroll
            for (int k = 0; k < 6; k++)
                o[k] = fmaf(v, sW2[r * 192 + lane + 32 * k], o[k]);
        }
#pragma unroll
        for (int k = 0; k < 6; k++) g_sproj[(size_t)n * 192 + lane + 32 * k] = o[k];
    }
}

// ================= spherical-harmonic invariants (streamed) =================
// Computes inv[l] = mean_m( Y_lm(e) * Y_lm(r) ), l = 0..6, without
// materializing the 49-component SH vectors. Per-m column recurrence.
__device__ __forceinline__ void sh_invariants(
    float xe, float ye, float ze, float xr, float yr, float zr, float* inv) {
    float nne = rsqrtf(xe * xe + ye * ye + ze * ze + 1e-12f);
    xe *= nne; ye *= nne; ze *= nne;
    float nnr = rsqrtf(xr * xr + yr * yr + zr * zr + 1e-12f);
    xr *= nnr; yr *= nnr; zr *= nnr;
    float st2e = xe * xe + ye * ye;
    float st2r = xr * xr + yr * yr;
    float ste = sqrtf(st2e), str = sqrtf(st2r);
    float c1e = (st2e > 0.0f) ? xe / ste : 0.0f;
    float s1e = (st2e > 0.0f) ? ye / ste : 0.0f;
    float c1r = (st2r > 0.0f) ? xr / str : 0.0f;
    float s1r = (st2r > 0.0f) ? yr / str : 0.0f;

    float acc[7];
#pragma unroll
    for (int l = 0; l < 7; l++) acc[l] = 0.0f;

    float de = 0.28209479177387814f, dr = 0.28209479177387814f;  // P(0,0)
    float ce = 1.0f, se = 0.0f, cr = 1.0f, sr = 0.0f;            // cos/sin(m*phi)
#pragma unroll
    for (int m = 0; m <= 6; m++) {
        if (m > 0) {
            float km = sqrtf((2.0f * m + 1.0f) / (2.0f * m));
            de = -km * ste * de;
            dr = -km * str * dr;
            float ce2 = c1e * ce - s1e * se; se = s1e * ce + c1e * se; ce = ce2;
            float cr2 = c1r * cr - s1r * sr; sr = s1r * cr + c1r * sr; cr = cr2;
        }
        float w = (m == 0) ? 1.0f : 2.0f * (ce * cr + se * sr);
        float pe1 = de, pr1 = dr;  // P(m,m)
        acc[m] += w * pe1 * pr1;
        if (m < 6) {
            float kp = sqrtf(2.0f * m + 3.0f);
            float pe = kp * ze * de;  // P(m+1,m)
            float pr = kp * zr * dr;
            acc[m + 1] += w * pe * pr;
            float pe0 = pe1, pr0 = pr1;
#pragma unroll
            for (int l = m + 2; l <= 6; l++) {
                float fl = (float)l;
                float a = sqrtf((4.0f * fl * fl - 1.0f) / (fl * fl - (float)(m * m)));
                float b = sqrtf(((fl - 1.0f) * (fl - 1.0f) - (float)(m * m)) /
                                (4.0f * (fl - 1.0f) * (fl - 1.0f) - 1.0f));
                float pen = a * (ze * pe - b * pe0); pe0 = pe; pe = pen;
                float prn = a * (zr * pr - b * pr0); pr0 = pr; pr = prn;
                acc[l] += w * pe * pr;
            }
        }
    }
    const float fourpi = 12.566370614359172f;
#pragma unroll
    for (int l = 0; l < 7; l++) inv[l] = acc[l] * (fourpi / (2.0f * l + 1.0f));
}

// ================= kernel 5: per-edge geometric features =================
__global__ void k_geom(const float* __restrict__ ud, const int* __restrict__ eidx,
                       const float* __restrict__ ln_g, const float* __restrict__ ln_b,
                       int E) {
    int e = blockIdx.x * blockDim.x + threadIdx.x;
    if (e >= E) return;
    float ux = ud[e * 3 + 0], uy = ud[e * 3 + 1], uz = ud[e * 3 + 2];
    int i = eidx[E + e];
    float rx = g_ref_vec[i * 3 + 0], ry = g_ref_vec[i * 3 + 1], rz = g_ref_vec[i * 3 + 2];
    float inv[7];
    sh_invariants(ux, uy, uz, rx, ry, rz, inv);
    float mu = 0.0f;
#pragma unroll
    for (int l = 0; l < 7; l++) mu += inv[l];
    mu *= (1.0f / 7.0f);
    float var = 0.0f;
#pragma unroll
    for (int l = 0; l < 7; l++) { float d = inv[l] - mu; var += d * d; }
    var *= (1.0f / 7.0f);
    float isd = rsqrtf(var + 1e-5f);
    g_geom[(size_t)e * 8 + 0] = ux * rx + uy * ry + uz * rz;  // cos_theta
#pragma unroll
    for (int l = 0; l < 7; l++)
        g_geom[(size_t)e * 8 + 1 + l] = (inv[l] - mu) * isd * ln_g[l] + ln_b[l];
}

// ================= kernel 6: main per-edge message + scatter =================
__global__ void __launch_bounds__(256)
k_main(const float* __restrict__ rbf, const float* __restrict__ ud,
       const int* __restrict__ eidx, const float* __restrict__ W_edge,
       const float* __restrict__ b_edge, const float* __restrict__ W_inv,
       const float* __restrict__ b_inv, const float* __restrict__ nv,
       float* __restrict__ out, int N, int E) {
    __shared__ float sWe[64 * 192];  // exactly 48KB
    int tid = threadIdx.x;
    for (int q = tid; q < 64 * 192; q += blockDim.x) sWe[q] = W_edge[q];
    __syncthreads();

    int lane = tid & 31, warp = tid >> 5;
    float* outv = out + (size_t)N * 64;

    // per-thread biases (columns c = lane + 32*k)
    float be[6], bi[6];
#pragma unroll
    for (int k = 0; k < 6; k++) {
        be[k] = b_edge[lane + 32 * k];
        bi[k] = b_inv[lane + 32 * k];
    }

    const float inv_sqrt3 = 0.57735026918962576f;
    const float inv_sqrt_h = 0.125f;

    int ntiles = (E + 3) >> 2;
    for (int t = blockIdx.x * 8 + warp; t < ntiles; t += gridDim.x * 8) {
        int e0 = t * 4;
        int ecnt = min(4, E - e0);

        float rb0[4], rb1[4];
        int jj[4], ii[4];
#pragma unroll
        for (int s = 0; s < 4; s++) {
            int e = e0 + ((s < ecnt) ? s : 0);
            rb0[s] = rbf[(size_t)e * 64 + lane];
            rb1[s] = rbf[(size_t)e * 64 + 32 + lane];
            jj[s] = eidx[e];
            ii[s] = eidx[E + e];
        }

        float acc[4][6];
#pragma unroll
        for (int s = 0; s < 4; s++)
#pragma unroll
            for (int k = 0; k < 6; k++) acc[s][k] = be[k];

#pragma unroll
        for (int r = 0; r < 64; r++) {
            float w[6];
#pragma unroll
            for (int k = 0; k < 6; k++) w[k] = sWe[r * 192 + lane + 32 * k];
#pragma unroll
            for (int s = 0; s < 4; s++) {
                float rv = __shfl_sync(0xffffffffu, (r < 32) ? rb0[s] : rb1[s], r & 31);
#pragma unroll
                for (int k = 0; k < 6; k++) acc[s][k] = fmaf(rv, w[k], acc[s][k]);
            }
        }

        for (int s = 0; s < ecnt; s++) {
            int e = e0 + s;
            int j = jj[s], i = ii[s];
            float gm[8];
#pragma unroll
            for (int q = 0; q < 8; q++) gm[q] = g_geom[(size_t)e * 8 + q];
            float x[6];
#pragma unroll
            for (int k = 0; k < 6; k++) {
                int c = lane + 32 * k;
                float g = bi[k];
#pragma unroll
                for (int q = 0; q < 8; q++) g = fmaf(gm[q], W_inv[q * 192 + c], g);
                float sg = g * (1.0f / (1.0f + __expf(-g))) * (1.0f / 0.6f);
                float gate = tanhf(sg);
                float rh = acc[s][k] * (1.0f + gate);
                x[k] = g_sproj[(size_t)j * 192 + c] * rh * inv_sqrt3;
            }
            // delta_scalar += x3
            atomicAdd(&out[(size_t)i * 64 + lane], x[4]);
            atomicAdd(&out[(size_t)i * 64 + 32 + lane], x[5]);
            // delta_vector += (x1*nv[j] + x2*ud) * inv_sqrt_h
            float u0 = ud[e * 3 + 0], u1 = ud[e * 3 + 1], u2 = ud[e * 3 + 2];
#pragma unroll
            for (int d = 0; d < 3; d++) {
                float udd = (d == 0) ? u0 : ((d == 1) ? u1 : u2);
                float nva = nv[(size_t)j * 192 + d * 64 + lane];
                float nvb = nv[(size_t)j * 192 + d * 64 + 32 + lane];
                atomicAdd(&outv[(size_t)i * 192 + d * 64 + lane],
                          (x[0] * nva + x[2] * udd) * inv_sqrt_h);
                atomicAdd(&outv[(size_t)i * 192 + d * 64 + 32 + lane],
                          (x[1] * nvb + x[3] * udd) * inv_sqrt_h);
            }
        }
    }
}

// ================= launch =================
extern "C" void kernel_launch(void* const* d_in, const int* in_sizes, int n_in,
                              void* d_out, int out_size) {
    const float* node_scalar = (const float*)d_in[0];
    const float* node_vector = (const float*)d_in[1];
    const float* edge_rbf    = (const float*)d_in[2];
    const float* edge_udiff  = (const float*)d_in[3];
    const int*   edge_index  = (const int*)d_in[4];
    const float* W_edge      = (const float*)d_in[5];
    const float* b_edge      = (const float*)d_in[6];
    const float* W_x1        = (const float*)d_in[7];
    const float* b_x1        = (const float*)d_in[8];
    const float* W_x2        = (const float*)d_in[9];
    const float* b_x2        = (const float*)d_in[10];
    const float* ln_g        = (const float*)d_in[11];
    const float* ln_b        = (const float*)d_in[12];
    const float* W_inv       = (const float*)d_in[13];
    const float* b_inv       = (const float*)d_in[14];

    int N = in_sizes[0] / H;
    int E = in_sizes[3] / 3;
    float* out = (float*)d_out;

    k_zero<<<1024, 256>>>(out, out_size, N);
    k_refaccum<<<(E + 255) / 256, 256>>>(edge_udiff, edge_index, E);
    k_refvec<<<(N + 255) / 256, 256>>>(N);
    k_sproj<<<296, 256>>>(node_scalar, W_x1, b_x1, W_x2, b_x2, N);
    k_geom<<<(E + 255) / 256, 256>>>(edge_udiff, edge_index, ln_g, ln_b, E);
    k_main<<<592, 256>>>(edge_rbf, edge_udiff, edge_index, W_edge, b_edge,
                         W_inv, b_inv, node_vector, out, N, E);
}

// round 2
// speedup vs baseline: 1.7778x; 1.7778x over previous
#include <cuda_runtime.h>
#include <math.h>

#define NMAX 50000
#define EMAX 400000

// ---- scratch (device globals; no allocation allowed) ----
__device__ float g_ref_accum[NMAX * 4];   // sum x,y,z + count
__device__ float g_ref_vec[NMAX * 3];
__device__ float g_sproj[(size_t)NMAX * 192];
__device__ float g_geom[(size_t)EMAX * 8];

// ---------------- helpers ----------------
__device__ __forceinline__ unsigned long long pk2(float lo, float hi) {
    unsigned long long r;
    asm("mov.b64 %0, {%1, %2};" : "=l"(r) : "f"(lo), "f"(hi));
    return r;
}
__device__ __forceinline__ void upk2(unsigned long long v, float& lo, float& hi) {
    asm("mov.b64 {%0, %1}, %2;" : "=f"(lo), "=f"(hi) : "l"(v));
}
__device__ __forceinline__ unsigned long long ffma2(unsigned long long a,
                                                    unsigned long long b,
                                                    unsigned long long c) {
    unsigned long long d;
    asm("fma.rn.f32x2 %0, %1, %2, %3;" : "=l"(d) : "l"(a), "l"(b), "l"(c));
    return d;
}
__device__ __forceinline__ float tanh_fast(float x) {
    float y;
    asm("tanh.approx.f32 %0, %1;" : "=f"(y) : "f"(x));
    return y;
}
__device__ __forceinline__ void red2(float* a, float x, float y) {
    asm volatile("red.global.add.v2.f32 [%0], {%1, %2};"
                 :: "l"(a), "f"(x), "f"(y) : "memory");
}
__device__ __forceinline__ void red4(float* a, float x, float y, float z, float w) {
    asm volatile("red.global.add.v4.f32 [%0], {%1, %2, %3, %4};"
                 :: "l"(a), "f"(x), "f"(y), "f"(z), "f"(w) : "memory");
}

// ================= kernel 1: zero output + accumulators (float4) =================
__global__ void k_zero(float4* __restrict__ out4, int n_out4, int n_acc4) {
    float4* acc4 = (float4*)g_ref_accum;
    int total = n_out4 + n_acc4;
    float4 z = make_float4(0.f, 0.f, 0.f, 0.f);
    for (int i = blockIdx.x * blockDim.x + threadIdx.x; i < total;
         i += gridDim.x * blockDim.x) {
        if (i < n_out4) out4[i] = z;
        else acc4[i - n_out4] = z;
    }
}

// ================= kernel 2: segment-sum of edge_udiff over i =================
__global__ void k_refaccum(const float* __restrict__ ud,
                           const int* __restrict__ eidx, int E) {
    int e = blockIdx.x * blockDim.x + threadIdx.x;
    if (e >= E) return;
    int i = eidx[E + e];
    red4(&g_ref_accum[i * 4], ud[e * 3 + 0], ud[e * 3 + 1], ud[e * 3 + 2], 1.0f);
}

// ================= kernel 3: normalize ref vector per node =================
__global__ void k_refvec(int N) {
    int n = blockIdx.x * blockDim.x + threadIdx.x;
    if (n >= N) return;
    float4 a = *(const float4*)&g_ref_accum[n * 4];
    float ic = 1.0f / fmaxf(a.w, 1.0f);
    float rx = a.x * ic, ry = a.y * ic, rz = a.z * ic;
    float norm = sqrtf(rx * rx + ry * ry + rz * rz + 1e-9f);
    float inm = 1.0f / norm;
    rx *= inm; ry *= inm; rz *= inm;
    if (norm < 5e-5f) { rx = 1.0f; ry = 0.0f; rz = 0.0f; }
    g_ref_vec[n * 3 + 0] = rx;
    g_ref_vec[n * 3 + 1] = ry;
    g_ref_vec[n * 3 + 2] = rz;
}

// ================= kernel 4: node scalar MLP projection =================
// 2 nodes per warp iteration; layer2 uses FFMA2 with column-pair ownership.
__global__ void __launch_bounds__(256)
k_sproj(const float* __restrict__ ns, const float* __restrict__ W1,
        const float* __restrict__ b1, const float* __restrict__ W2,
        const float* __restrict__ b2, int N) {
    __shared__ float sW1[64 * 32];
    __shared__ float sW2[32 * 192];
    int tid = threadIdx.x;
    for (int q = tid; q < 64 * 32; q += 256) sW1[q] = W1[q];
    for (int q = tid; q < 32 * 192; q += 256) sW2[q] = W2[q];
    __syncthreads();
    const unsigned long long* sW2u = (const unsigned long long*)sW2;
    const float2* b2p = (const float2*)b2;
    int lane = tid & 31, warp = tid >> 5;

    unsigned long long bb[3];
#pragma unroll
    for (int k = 0; k < 3; k++) {
        float2 t = b2p[lane + 32 * k];
        bb[k] = pk2(t.x, t.y);
    }
    float b1v = b1[lane];

    int npairs = (N + 1) >> 1;
    for (int p = blockIdx.x * 8 + warp; p < npairs; p += gridDim.x * 8) {
        int nA = p * 2;
        int nB = min(nA + 1, N - 1);
        float aA0 = ns[(size_t)nA * 64 + lane], aA1 = ns[(size_t)nA * 64 + 32 + lane];
        float aB0 = ns[(size_t)nB * 64 + lane], aB1 = ns[(size_t)nB * 64 + 32 + lane];
        float tA = b1v, tB = b1v;
#pragma unroll
        for (int r = 0; r < 64; r++) {
            float w = sW1[r * 32 + lane];
            float vA = __shfl_sync(0xffffffffu, (r < 32) ? aA0 : aA1, r & 31);
            float vB = __shfl_sync(0xffffffffu, (r < 32) ? aB0 : aB1, r & 31);
            tA = fmaf(vA, w, tA);
            tB = fmaf(vB, w, tB);
        }
        tA = __fdividef(tA, 1.0f + __expf(-tA)) * (1.0f / 0.6f);
        tB = __fdividef(tB, 1.0f + __expf(-tB)) * (1.0f / 0.6f);
        unsigned long long oA[3], oB[3];
#pragma unroll
        for (int k = 0; k < 3; k++) { oA[k] = bb[k]; oB[k] = bb[k]; }
#pragma unroll
        for (int r = 0; r < 32; r++) {
            unsigned long long w0 = sW2u[r * 96 + lane];
            unsigned long long w1 = sW2u[r * 96 + 32 + lane];
            unsigned long long w2 = sW2u[r * 96 + 64 + lane];
            float vA = __shfl_sync(0xffffffffu, tA, r);
            float vB = __shfl_sync(0xffffffffu, tB, r);
            unsigned long long vvA = pk2(vA, vA), vvB = pk2(vB, vB);
            oA[0] = ffma2(vvA, w0, oA[0]);
            oA[1] = ffma2(vvA, w1, oA[1]);
            oA[2] = ffma2(vvA, w2, oA[2]);
            oB[0] = ffma2(vvB, w0, oB[0]);
            oB[1] = ffma2(vvB, w1, oB[1]);
            oB[2] = ffma2(vvB, w2, oB[2]);
        }
        unsigned long long* outA = (unsigned long long*)g_sproj + (size_t)nA * 96;
#pragma unroll
        for (int k = 0; k < 3; k++) outA[lane + 32 * k] = oA[k];
        if (nB != nA) {
            unsigned long long* outB = (unsigned long long*)g_sproj + (size_t)nB * 96;
#pragma unroll
            for (int k = 0; k < 3; k++) outB[lane + 32 * k] = oB[k];
        }
    }
}

// ================= spherical-harmonic invariants (streamed) =================
__device__ __forceinline__ void sh_invariants(
    float xe, float ye, float ze, float xr, float yr, float zr, float* inv) {
    float nne = rsqrtf(xe * xe + ye * ye + ze * ze + 1e-12f);
    xe *= nne; ye *= nne; ze *= nne;
    float nnr = rsqrtf(xr * xr + yr * yr + zr * zr + 1e-12f);
    xr *= nnr; yr *= nnr; zr *= nnr;
    float st2e = xe * xe + ye * ye;
    float st2r = xr * xr + yr * yr;
    float ste = sqrtf(st2e), str = sqrtf(st2r);
    float c1e = (st2e > 0.0f) ? xe / ste : 0.0f;
    float s1e = (st2e > 0.0f) ? ye / ste : 0.0f;
    float c1r = (st2r > 0.0f) ? xr / str : 0.0f;
    float s1r = (st2r > 0.0f) ? yr / str : 0.0f;

    float acc[7];
#pragma unroll
    for (int l = 0; l < 7; l++) acc[l] = 0.0f;

    float de = 0.28209479177387814f, dr = 0.28209479177387814f;
    float ce = 1.0f, se = 0.0f, cr = 1.0f, sr = 0.0f;
#pragma unroll
    for (int m = 0; m <= 6; m++) {
        if (m > 0) {
            float km = sqrtf((2.0f * m + 1.0f) / (2.0f * m));
            de = -km * ste * de;
            dr = -km * str * dr;
            float ce2 = c1e * ce - s1e * se; se = s1e * ce + c1e * se; ce = ce2;
            float cr2 = c1r * cr - s1r * sr; sr = s1r * cr + c1r * sr; cr = cr2;
        }
        float w = (m == 0) ? 1.0f : 2.0f * (ce * cr + se * sr);
        float pe1 = de, pr1 = dr;
        acc[m] += w * pe1 * pr1;
        if (m < 6) {
            float kp = sqrtf(2.0f * m + 3.0f);
            float pe = kp * ze * de;
            float pr = kp * zr * dr;
            acc[m + 1] += w * pe * pr;
            float pe0 = pe1, pr0 = pr1;
#pragma unroll
            for (int l = m + 2; l <= 6; l++) {
                float fl = (float)l;
                float a = sqrtf((4.0f * fl * fl - 1.0f) / (fl * fl - (float)(m * m)));
                float b = sqrtf(((fl - 1.0f) * (fl - 1.0f) - (float)(m * m)) /
                                (4.0f * (fl - 1.0f) * (fl - 1.0f) - 1.0f));
                float pen = a * (ze * pe - b * pe0); pe0 = pe; pe = pen;
                float prn = a * (zr * pr - b * pr0); pr0 = pr; pr = prn;
                acc[l] += w * pe * pr;
            }
        }
    }
    const float fourpi = 12.566370614359172f;
#pragma unroll
    for (int l = 0; l < 7; l++) inv[l] = acc[l] * (fourpi / (2.0f * l + 1.0f));
}

// ================= kernel 5: per-edge geometric features =================
__global__ void k_geom(const float* __restrict__ ud, const int* __restrict__ eidx,
                       const float* __restrict__ ln_g, const float* __restrict__ ln_b,
                       int E) {
    int e = blockIdx.x * blockDim.x + threadIdx.x;
    if (e >= E) return;
    float ux = ud[e * 3 + 0], uy = ud[e * 3 + 1], uz = ud[e * 3 + 2];
    int i = __ldg(&eidx[E + e]);
    float rx = __ldg(&g_ref_vec[i * 3 + 0]);
    float ry = __ldg(&g_ref_vec[i * 3 + 1]);
    float rz = __ldg(&g_ref_vec[i * 3 + 2]);
    float inv[7];
    sh_invariants(ux, uy, uz, rx, ry, rz, inv);
    float mu = 0.0f;
#pragma unroll
    for (int l = 0; l < 7; l++) mu += inv[l];
    mu *= (1.0f / 7.0f);
    float var = 0.0f;
#pragma unroll
    for (int l = 0; l < 7; l++) { float d = inv[l] - mu; var += d * d; }
    var *= (1.0f / 7.0f);
    float isd = rsqrtf(var + 1e-5f);
    float o[8];
    o[0] = ux * rx + uy * ry + uz * rz;
#pragma unroll
    for (int l = 0; l < 7; l++)
        o[1 + l] = (inv[l] - mu) * isd * ln_g[l] + ln_b[l];
    float4* gg = (float4*)(g_geom + (size_t)e * 8);
    gg[0] = make_float4(o[0], o[1], o[2], o[3]);
    gg[1] = make_float4(o[4], o[5], o[6], o[7]);
}

// ================= kernel 6: main per-edge message + scatter =================
// 8-edge tiles per warp, FFMA2 GEMV, per-warp transpose + vector red.
__global__ void __launch_bounds__(256, 2)
k_main(const float* __restrict__ rbf, const float* __restrict__ ud,
       const int* __restrict__ eidx, const float* __restrict__ W_edge,
       const float* __restrict__ b_edge, const float* __restrict__ W_inv,
       const float* __restrict__ b_inv, const float* __restrict__ nv,
       float* __restrict__ out, int N, int E) {
    extern __shared__ float dsm[];
    float* sWe = dsm;                            // 64*192 floats = 48KB
    float4* sXbuf = (float4*)(dsm + 64 * 192);   // 8 warps * 32 float4 = 4KB

    int tid = threadIdx.x;
    for (int q = tid; q < 64 * 192 / 4; q += 256)
        ((float4*)sWe)[q] = ((const float4*)W_edge)[q];
    __syncthreads();
    const unsigned long long* sWe64 = (const unsigned long long*)sWe;

    int lane = tid & 31, warp = tid >> 5;
    float* outv = out + (size_t)N * 64;
    float4* xwarp = &sXbuf[warp * 32];

    unsigned long long be2[3], bi2[3];
    const float2* be2p = (const float2*)b_edge;
    const float2* bi2p = (const float2*)b_inv;
#pragma unroll
    for (int k = 0; k < 3; k++) {
        float2 t = be2p[lane + 32 * k]; be2[k] = pk2(t.x, t.y);
        float2 u = bi2p[lane + 32 * k]; bi2[k] = pk2(u.x, u.y);
    }
    const float2* Winv2 = (const float2*)W_inv;
    const float2* sp2 = (const float2*)g_sproj;

    const float inv_sqrt3 = 0.57735026918962576f;
    const float ish = 0.125f;

    int ntiles = (E + 7) >> 3;
    for (int t = blockIdx.x * 8 + warp; t < ntiles; t += gridDim.x * 8) {
        int e0 = t * 8;
        int ecnt = min(8, E - e0);

        float rb0[8], rb1[8];
        int jj[8], ii[8];
#pragma unroll
        for (int s = 0; s < 8; s++) {
            int e = e0 + ((s < ecnt) ? s : 0);
            rb0[s] = rbf[(size_t)e * 64 + lane];
            rb1[s] = rbf[(size_t)e * 64 + 32 + lane];
            jj[s] = eidx[e];
            ii[s] = eidx[E + e];
        }

        unsigned long long acc[8][3];
#pragma unroll
        for (int s = 0; s < 8; s++) {
            acc[s][0] = be2[0]; acc[s][1] = be2[1]; acc[s][2] = be2[2];
        }

#pragma unroll
        for (int r = 0; r < 64; r++) {
            unsigned long long w0 = sWe64[r * 96 + lane];
            unsigned long long w1 = sWe64[r * 96 + 32 + lane];
            unsigned long long w2 = sWe64[r * 96 + 64 + lane];
#pragma unroll
            for (int s = 0; s < 8; s++) {
                float rv = __shfl_sync(0xffffffffu, (r < 32) ? rb0[s] : rb1[s], r & 31);
                unsigned long long rvv = pk2(rv, rv);
                acc[s][0] = ffma2(rvv, w0, acc[s][0]);
                acc[s][1] = ffma2(rvv, w1, acc[s][1]);
                acc[s][2] = ffma2(rvv, w2, acc[s][2]);
            }
        }

        for (int s = 0; s < ecnt; s++) {
            int e = e0 + s, j = jj[s], i = ii[s];
            float4 gA = *(const float4*)(g_geom + (size_t)e * 8);
            float4 gB = *(const float4*)(g_geom + (size_t)e * 8 + 4);
            unsigned long long gp[8];
            gp[0] = pk2(gA.x, gA.x); gp[1] = pk2(gA.y, gA.y);
            gp[2] = pk2(gA.z, gA.z); gp[3] = pk2(gA.w, gA.w);
            gp[4] = pk2(gB.x, gB.x); gp[5] = pk2(gB.y, gB.y);
            gp[6] = pk2(gB.z, gB.z); gp[7] = pk2(gB.w, gB.w);

            float xv[6];
#pragma unroll
            for (int k2 = 0; k2 < 3; k2++) {
                int m = lane + 32 * k2;
                unsigned long long g = bi2[k2];
#pragma unroll
                for (int q = 0; q < 8; q++) {
                    float2 wv = __ldg(&Winv2[q * 96 + m]);
                    g = ffma2(gp[q], pk2(wv.x, wv.y), g);
                }
                float g0, g1; upk2(g, g0, g1);
                float sg0 = __fdividef(g0, 1.0f + __expf(-g0)) * (1.0f / 0.6f);
                float sg1 = __fdividef(g1, 1.0f + __expf(-g1)) * (1.0f / 0.6f);
                float f0 = 1.0f + tanh_fast(sg0);
                float f1 = 1.0f + tanh_fast(sg1);
                float a0, a1; upk2(acc[s][k2], a0, a1);
                float2 sp = __ldg(&sp2[(size_t)j * 96 + m]);
                xv[2 * k2 + 0] = sp.x * a0 * f0 * inv_sqrt3;
                xv[2 * k2 + 1] = sp.y * a1 * f1 * inv_sqrt3;
            }
            // x3 -> delta_scalar directly (cols 2*lane, 2*lane+1)
            red2(&out[(size_t)i * 64 + 2 * lane], xv[4], xv[5]);
            // stash (x1,x2) pairs: {x1[2L], x2[2L], x1[2L+1], x2[2L+1]}
            xwarp[lane] = make_float4(xv[0], xv[2], xv[1], xv[3]);
            __syncwarp();

            float u0 = ud[e * 3 + 0], u1 = ud[e * 3 + 1], u2 = ud[e * 3 + 2];
            const float4* xp4 = (const float4*)xwarp;  // xp4[k] = pairs 2k, 2k+1
            // round 1: outputs o = 4*lane in [0,128)  (d = 0 or 1)
            {
                int o = 4 * lane;
                int q = o & 63;
                float udd = (o >> 6) ? u1 : u0;
                float4 pa = xp4[q >> 1], pb = xp4[(q >> 1) + 1];
                float4 nvv = *(const float4*)(nv + (size_t)j * 192 + o);
                float v0 = (pa.x * nvv.x + pa.y * udd) * ish;
                float v1 = (pa.z * nvv.y + pa.w * udd) * ish;
                float v2 = (pb.x * nvv.z + pb.y * udd) * ish;
                float v3 = (pb.z * nvv.w + pb.w * udd) * ish;
                red4(&outv[(size_t)i * 192 + o], v0, v1, v2, v3);
            }
            // round 2: lanes < 16 cover o = 128 + 4*lane (d = 2)
            if (lane < 16) {
                int o = 128 + 4 * lane;
                int q = 4 * lane;
                float4 pa = xp4[q >> 1], pb = xp4[(q >> 1) + 1];
                float4 nvv = *(const float4*)(nv + (size_t)j * 192 + o);
                float v0 = (pa.x * nvv.x + pa.y * u2) * ish;
                float v1 = (pa.z * nvv.y + pa.w * u2) * ish;
                float v2 = (pb.x * nvv.z + pb.y * u2) * ish;
                float v3 = (pb.z * nvv.w + pb.w * u2) * ish;
                red4(&outv[(size_t)i * 192 + o], v0, v1, v2, v3);
            }
            __syncwarp();
        }
    }
}

// ================= launch =================
extern "C" void kernel_launch(void* const* d_in, const int* in_sizes, int n_in,
                              void* d_out, int out_size) {
    const float* node_scalar = (const float*)d_in[0];
    const float* node_vector = (const float*)d_in[1];
    const float* edge_rbf    = (const float*)d_in[2];
    const float* edge_udiff  = (const float*)d_in[3];
    const int*   edge_index  = (const int*)d_in[4];
    const float* W_edge      = (const float*)d_in[5];
    const float* b_edge      = (const float*)d_in[6];
    const float* W_x1        = (const float*)d_in[7];
    const float* b_x1        = (const float*)d_in[8];
    const float* W_x2        = (const float*)d_in[9];
    const float* b_x2        = (const float*)d_in[10];
    const float* ln_g        = (const float*)d_in[11];
    const float* ln_b        = (const float*)d_in[12];
    const float* W_inv       = (const float*)d_in[13];
    const float* b_inv       = (const float*)d_in[14];

    int N = in_sizes[0] / 64;
    int E = in_sizes[3] / 3;
    float* out = (float*)d_out;

    int smem_main = 64 * 192 * 4 + 8 * 32 * 16;  // 48KB W_edge + 4KB xbuf
    cudaFuncSetAttribute(k_main, cudaFuncAttributeMaxDynamicSharedMemorySize,
                         smem_main);

    k_zero<<<1024, 256>>>((float4*)out, out_size / 4, N);
    k_refaccum<<<(E + 255) / 256, 256>>>(edge_udiff, edge_index, E);
    k_refvec<<<(N + 255) / 256, 256>>>(N);
    k_sproj<<<296, 256>>>(node_scalar, W_x1, b_x1, W_x2, b_x2, N);
    k_geom<<<(E + 255) / 256, 256>>>(edge_udiff, edge_index, ln_g, ln_b, E);
    k_main<<<296, 256, smem_main>>>(edge_rbf, edge_udiff, edge_index, W_edge,
                                    b_edge, W_inv, b_inv, node_vector, out, N, E);
}